// round 1
// baseline (speedup 1.0000x reference)
#include <cuda_runtime.h>

// Gaussian_Forward_Model: 3x3 conv, padding=1 (zeros), kernel built from
// weight (clamped) * weight_factor (clamped), rounded (RNE), min-clamped.
// input: [B=64, C=1, H=512, W=512] fp32
// weight: [N_MULT, 9], weight_factor: [N_MULT, 1]
// output: [N_MULT, B, 1, H, W] fp32

#define B 64
#define H 512
#define W 512
#define ROWS_PER_THREAD 8   // output rows per thread
#define TPB 128             // threads per block; 128 * 4 floats = 512 = W

__device__ __forceinline__ float clampf(float v, float lo, float hi) {
    return fminf(fmaxf(v, lo), hi);
}

struct Row {
    float l;    // x-1
    float4 c;   // x..x+3
    float r;    // x+4
};

__device__ __forceinline__ Row load_row(const float* __restrict__ img, int y, int x) {
    Row row;
    if (y < 0 || y >= H) {
        row.l = 0.f; row.r = 0.f;
        row.c = make_float4(0.f, 0.f, 0.f, 0.f);
        return row;
    }
    const float* p = img + (size_t)y * W + x;
    row.c = *reinterpret_cast<const float4*>(p);
    row.l = (x > 0)      ? p[-1] : 0.f;
    row.r = (x + 4 < W)  ? p[4]  : 0.f;
    return row;
}

__device__ __forceinline__ float4 hconv(const Row& row, float wl, float wc, float wr) {
    float4 o;
    o.x = fmaf(wl, row.l,   fmaf(wc, row.c.x, wr * row.c.y));
    o.y = fmaf(wl, row.c.x, fmaf(wc, row.c.y, wr * row.c.z));
    o.z = fmaf(wl, row.c.y, fmaf(wc, row.c.z, wr * row.c.w));
    o.w = fmaf(wl, row.c.z, fmaf(wc, row.c.w, wr * row.r));
    return o;
}

__global__ __launch_bounds__(TPB) void gauss3x3_kernel(
    const float* __restrict__ input,
    const float* __restrict__ weight,
    const float* __restrict__ weight_factor,
    float* __restrict__ output,
    int n_mult)
{
    // blockIdx.z encodes (m, b); blockIdx.y = row strip; threadIdx.x = float4 column
    int z = blockIdx.z;
    int b = z % B;
    int m = z / B;

    // Build the 9-tap kernel (matches reference clamp/round semantics).
    float wf = weight_factor[m];
    wf = clampf(wf, 1.001f, 254.999f);
    wf = clampf(wf, 1.0f, 255.0f);
    float w[9];
#pragma unroll
    for (int k = 0; k < 9; k++) {
        float wc = weight[m * 9 + k];
        wc = clampf(wc, 0.001f, 0.999f);
        wc = clampf(wc, 0.0f, 1.0f);
        float q = rintf(wc * wf);          // RNE, same as jnp.round
        w[k] = fmaxf(q, 0.001f);
    }

    const float* img = input + (size_t)b * H * W;
    float* out = output + ((size_t)m * B + b) * H * W;

    int x  = threadIdx.x * 4;
    int y0 = blockIdx.y * ROWS_PER_THREAD;

    Row ra = load_row(img, y0 - 1, x);  // row y-1
    Row rb = load_row(img, y0,     x);  // row y

#pragma unroll
    for (int i = 0; i < ROWS_PER_THREAD; i++) {
        int y = y0 + i;
        Row rc = load_row(img, y + 1, x);   // row y+1

        float4 top = hconv(ra, w[0], w[1], w[2]);
        float4 mid = hconv(rb, w[3], w[4], w[5]);
        float4 bot = hconv(rc, w[6], w[7], w[8]);

        float4 o;
        o.x = top.x + mid.x + bot.x;
        o.y = top.y + mid.y + bot.y;
        o.z = top.z + mid.z + bot.z;
        o.w = top.w + mid.w + bot.w;

        *reinterpret_cast<float4*>(out + (size_t)y * W + x) = o;

        ra = rb;
        rb = rc;
    }
}

extern "C" void kernel_launch(void* const* d_in, const int* in_sizes, int n_in,
                              void* d_out, int out_size) {
    const float* input  = (const float*)d_in[0];
    const float* weight = (const float*)d_in[1];
    const float* wfac   = (const float*)d_in[2];
    float* output       = (float*)d_out;

    int n_mult = in_sizes[1] / 9;   // = 1 for this shape

    dim3 block(TPB, 1, 1);
    dim3 grid(1, H / ROWS_PER_THREAD, B * n_mult);
    gauss3x3_kernel<<<grid, block>>>(input, weight, wfac, output, n_mult);
}